// round 4
// baseline (speedup 1.0000x reference)
#include <cuda_runtime.h>

#define G 1024
#define BATCH 4
#define ROWS_PER_CHUNK 19
#define GRID_Y ((G - 1 + ROWS_PER_CHUNK - 1) / ROWS_PER_CHUNK)   // 54

// E = 1023*1023 + 1022*1023 + 1023*1022 = 3,137,541 ; N = B*E
#define N_TOTAL 12550164.0

__device__ double g_acc = 0.0;
__device__ unsigned int g_done = 0;

struct V3 { float x, y, z; };

__device__ __forceinline__ V3 vsub(V3 a, V3 b) {
    V3 r; r.x = a.x - b.x; r.y = a.y - b.y; r.z = a.z - b.z; return r;
}
__device__ __forceinline__ V3 vcross(V3 a, V3 b) {
    V3 r;
    r.x = fmaf(a.y, b.z, -a.z * b.y);
    r.y = fmaf(a.z, b.x, -a.x * b.z);
    r.z = fmaf(a.x, b.y, -a.y * b.x);
    return r;
}
__device__ __forceinline__ float vdot(V3 a, V3 b) {
    return fmaf(a.x, b.x, fmaf(a.y, b.y, a.z * b.z));
}
__device__ __forceinline__ float qclamp(V3 a) {
    return fmaxf(vdot(a, a), 1e-16f);   // == max(|a|,1e-8)^2
}
__device__ __forceinline__ V3 ldv(const float* __restrict__ p) {
    V3 r; r.x = p[0]; r.y = p[1]; r.z = p[2]; return r;
}

__global__ void __launch_bounds__(256, 6)
nc_fused_kernel(const float* __restrict__ x, float* __restrict__ out,
                unsigned int nblocks) {
    const int c  = blockIdx.x * blockDim.x + threadIdx.x;   // column (0..1022 valid)
    const int r0 = blockIdx.y * ROWS_PER_CHUNK;
    const int bb = blockIdx.z;

    float sum_cos = 0.0f;   // loss = 1 - sum_cos_total / N_TOTAL
    if (c < G - 1) {
        const float* __restrict__ base = x + (size_t)bb * (size_t)G * G * 3;
        const int r1 = min(r0 + ROWS_PER_CHUNK, G - 1);
        const bool has_left = (c >= 1);

        const float* __restrict__ row = base + ((size_t)r0 * G + c) * 3;

        V3 p00 = ldv(row);
        V3 p01 = ldv(row + 3);
        V3 pl  = has_left ? ldv(row - 3) : V3{0.f, 0.f, 0.f};
        V3 pm  = (r0 >= 1) ? ldv(row - G * 3) : V3{0.f, 0.f, 0.f};

        for (int r = r0; r < r1; ++r) {
            const float* __restrict__ nrow = row + G * 3;
            V3 p10 = ldv(nrow);
            V3 p11 = ldv(nrow + 3);
            V3 pln = has_left ? ldv(nrow - 3) : V3{0.f, 0.f, 0.f};

            V3 e1 = vsub(p01, p00);
            V3 e2 = vsub(p10, p00);
            V3 d  = vsub(p11, p00);

            V3 cA = vcross(d, e1);    // diag n0 ;  horiz n0 = -cA
            V3 cB = vcross(e2, d);    // diag n1 ;  vert  n0 =  cB
            float qA = qclamp(cA);
            float qB = qclamp(cB);

            // diagonal: cos = dot(cA,cB)/ (|cA||cB|)
            sum_cos = fmaf(vdot(cA, cB), rsqrtf(qA * qB), sum_cos);

            if (r >= 1) {             // horizontal: n1 = cross(pm-p00, e1)
                V3 cH = vcross(vsub(pm, p00), e1);
                float qH = qclamp(cH);
                sum_cos = fmaf(-vdot(cA, cH), rsqrtf(qA * qH), sum_cos);
            }
            if (has_left) {           // vertical: n1 = cross(pl-p00, e2)
                V3 cV = vcross(vsub(pl, p00), e2);
                float qV = qclamp(cV);
                sum_cos = fmaf(vdot(cB, cV), rsqrtf(qB * qV), sum_cos);
            }

            pm = p00; p00 = p10; p01 = p11; pl = pln;
            row = nrow;
        }
    }

    // ---- block reduction ----
    #pragma unroll
    for (int off = 16; off > 0; off >>= 1)
        sum_cos += __shfl_down_sync(0xFFFFFFFFu, sum_cos, off);

    __shared__ float warp_sums[8];
    const int lane = threadIdx.x & 31;
    const int wid  = threadIdx.x >> 5;
    if (lane == 0) warp_sums[wid] = sum_cos;
    __syncthreads();

    __shared__ bool is_last;
    if (wid == 0) {
        float s = (lane < (blockDim.x >> 5)) ? warp_sums[lane] : 0.0f;
        #pragma unroll
        for (int off = 4; off > 0; off >>= 1)
            s += __shfl_down_sync(0xFFFFFFFFu, s, off);
        if (lane == 0) {
            atomicAdd(&g_acc, (double)s);
            __threadfence();
            unsigned int done = atomicInc(&g_done, nblocks - 1);
            is_last = (done == nblocks - 1);
        }
    }
    __syncthreads();

    if (is_last && threadIdx.x == 0) {
        double acc = atomicAdd(&g_acc, 0.0);       // coherent read
        out[0] = (float)(1.0 - acc / N_TOTAL);     // loss = 1 - mean(cos)
        __threadfence();
        g_acc = 0.0;                                // g_done wrapped to 0 via atomicInc
    }
}

extern "C" void kernel_launch(void* const* d_in, const int* in_sizes, int n_in,
                              void* d_out, int out_size) {
    const float* x = (const float*)d_in[0];
    float* out = (float*)d_out;

    dim3 block(256, 1, 1);
    dim3 grid((G - 1 + 255) / 256,   // 4
              GRID_Y,                // 54
              BATCH);                // 4  -> 864 blocks (one wave @ 6 CTA/SM)
    unsigned int nblocks = grid.x * grid.y * grid.z;
    nc_fused_kernel<<<grid, block>>>(x, out, nblocks);
}

// round 5
// speedup vs baseline: 1.2338x; 1.2338x over previous
#include <cuda_runtime.h>

#define G 1024
#define BATCH 4
#define ROWS 23
#define GRID_Y 45          // 44 full chunks of 23 + one chunk of 11 (44*23+11=1023)
#define ROWSTRIDE (G * 3)  // floats per grid row

// E = 1023*1023 + 1022*1023 + 1023*1022 = 3,137,541 ; N = B*E
#define N_TOTAL 12550164.0

__device__ double g_acc = 0.0;
__device__ unsigned int g_done = 0;

struct V3 { float x, y, z; };

__device__ __forceinline__ V3 vsub(V3 a, V3 b) {
    V3 r; r.x = a.x - b.x; r.y = a.y - b.y; r.z = a.z - b.z; return r;
}
__device__ __forceinline__ V3 vcross(V3 a, V3 b) {
    V3 r;
    r.x = fmaf(a.y, b.z, -a.z * b.y);
    r.y = fmaf(a.z, b.x, -a.x * b.z);
    r.z = fmaf(a.x, b.y, -a.y * b.x);
    return r;
}
__device__ __forceinline__ float vdot(V3 a, V3 b) {
    return fmaf(a.x, b.x, fmaf(a.y, b.y, a.z * b.z));
}
__device__ __forceinline__ float qclamp(V3 a) {
    return fmaxf(vdot(a, a), 1e-16f);   // == max(|a|,1e-8)^2
}
__device__ __forceinline__ V3 ldv(const float* __restrict__ p) {
    V3 r; r.x = p[0]; r.y = p[1]; r.z = p[2]; return r;
}

// Full body for a row r>=1: all three edges. Rolls state by value.
struct RowState {
    const float* row;
    V3 p00, p01, pl, pm;
};

__device__ __forceinline__ float row_full(RowState& s, int offL, float maskL) {
    const float* __restrict__ nrow = s.row + ROWSTRIDE;
    V3 p10 = ldv(nrow);
    V3 p11 = ldv(nrow + 3);
    V3 pln = ldv(nrow + offL);

    V3 e1 = vsub(s.p01, s.p00);
    V3 e2 = vsub(p10,  s.p00);
    V3 d  = vsub(p11,  s.p00);

    V3 cA = vcross(d, e1);          // diag n0 ; horiz n0 = -cA
    V3 cB = vcross(e2, d);          // diag n1 ; vert  n0 =  cB
    float qA = qclamp(cA);
    float qB = qclamp(cB);

    float r0 = vdot(cA, cB) * rsqrtf(qA * qB);                    // diagonal

    V3 cH = vcross(vsub(s.pm, s.p00), e1);
    float qH = qclamp(cH);
    float r1 = -vdot(cA, cH) * rsqrtf(qA * qH);                   // horizontal

    V3 cV = vcross(vsub(s.pl, s.p00), e2);
    float qV = qclamp(cV);
    float r2 = maskL * vdot(cB, cV) * rsqrtf(qB * qV);            // vertical

    s.pm = s.p00; s.p00 = p10; s.p01 = p11; s.pl = pln; s.row = nrow;
    return r0 + r1 + r2;
}

// Row 0 body: no horizontal edge.
__device__ __forceinline__ float row_zero(RowState& s, int offL, float maskL) {
    const float* __restrict__ nrow = s.row + ROWSTRIDE;
    V3 p10 = ldv(nrow);
    V3 p11 = ldv(nrow + 3);
    V3 pln = ldv(nrow + offL);

    V3 e1 = vsub(s.p01, s.p00);
    V3 e2 = vsub(p10,  s.p00);
    V3 d  = vsub(p11,  s.p00);

    V3 cA = vcross(d, e1);
    V3 cB = vcross(e2, d);
    float qA = qclamp(cA);
    float qB = qclamp(cB);

    float r0 = vdot(cA, cB) * rsqrtf(qA * qB);

    V3 cV = vcross(vsub(s.pl, s.p00), e2);
    float qV = qclamp(cV);
    float r2 = maskL * vdot(cB, cV) * rsqrtf(qB * qV);

    s.pm = s.p00; s.p00 = p10; s.p01 = p11; s.pl = pln; s.row = nrow;
    return r0 + r2;
}

__global__ void __launch_bounds__(256, 5)
nc_fused_kernel(const float* __restrict__ x, float* __restrict__ out,
                unsigned int nblocks) {
    const int c  = blockIdx.x * blockDim.x + threadIdx.x;   // 0..1022 valid
    const int r0 = blockIdx.y * ROWS;
    const int bb = blockIdx.z;

    float sum_cos = 0.0f;   // loss = 1 - sum_cos_total / N_TOTAL
    if (c < G - 1) {
        const float* __restrict__ base = x + (size_t)bb * (size_t)G * G * 3;
        const int offL   = (c >= 1) ? -3 : 0;      // c==0: reads own vertex -> zero vec, masked
        const float maskL = (c >= 1) ? 1.0f : 0.0f;

        RowState s;
        s.row = base + ((size_t)r0 * G + c) * 3;
        s.p00 = ldv(s.row);
        s.p01 = ldv(s.row + 3);
        s.pl  = ldv(s.row + offL);

        if (r0 == 0) {
            // peel row 0 (diag + vertical), then 22 full rows, compile-time trip
            sum_cos += row_zero(s, offL, maskL);
            #pragma unroll 2
            for (int i = 0; i < ROWS - 1; ++i)
                sum_cos += row_full(s, offL, maskL);
        } else {
            s.pm = ldv(s.row - ROWSTRIDE);
            const int nrows = min(ROWS, (G - 1) - r0);
            if (nrows == ROWS) {
                #pragma unroll 2
                for (int i = 0; i < ROWS; ++i)
                    sum_cos += row_full(s, offL, maskL);
            } else {
                for (int i = 0; i < nrows; ++i)
                    sum_cos += row_full(s, offL, maskL);
            }
        }
    }

    // ---- block reduction ----
    #pragma unroll
    for (int off = 16; off > 0; off >>= 1)
        sum_cos += __shfl_down_sync(0xFFFFFFFFu, sum_cos, off);

    __shared__ float warp_sums[8];
    const int lane = threadIdx.x & 31;
    const int wid  = threadIdx.x >> 5;
    if (lane == 0) warp_sums[wid] = sum_cos;
    __syncthreads();

    __shared__ bool is_last;
    if (wid == 0) {
        float s = (lane < (blockDim.x >> 5)) ? warp_sums[lane] : 0.0f;
        #pragma unroll
        for (int off = 4; off > 0; off >>= 1)
            s += __shfl_down_sync(0xFFFFFFFFu, s, off);
        if (lane == 0) {
            atomicAdd(&g_acc, (double)s);
            __threadfence();
            unsigned int done = atomicInc(&g_done, nblocks - 1);
            is_last = (done == nblocks - 1);
        }
    }
    __syncthreads();

    if (is_last && threadIdx.x == 0) {
        double acc = atomicAdd(&g_acc, 0.0);       // coherent read
        out[0] = (float)(1.0 - acc / N_TOTAL);     // loss = 1 - mean(cos)
        __threadfence();
        g_acc = 0.0;                                // g_done wrapped via atomicInc
    }
}

extern "C" void kernel_launch(void* const* d_in, const int* in_sizes, int n_in,
                              void* d_out, int out_size) {
    const float* x = (const float*)d_in[0];
    float* out = (float*)d_out;

    dim3 block(256, 1, 1);
    dim3 grid((G - 1 + 255) / 256,   // 4
              GRID_Y,                // 45
              BATCH);                // 4  -> 720 blocks (one wave @ 5 CTA/SM)
    unsigned int nblocks = grid.x * grid.y * grid.z;
    nc_fused_kernel<<<grid, block>>>(x, out, nblocks);
}

// round 6
// speedup vs baseline: 1.4562x; 1.1802x over previous
#include <cuda_runtime.h>

#define G 1024
#define BATCH 4
#define ROWS 24
#define NCHUNK 43              // 42*24=1008, last chunk 15 rows (1023 total)
#define NSTRIP 33              // 33 warps * 31 quads = 1023 columns
#define ROWSTRIDE (G * 3)
#define TOTWARPS (NSTRIP * NCHUNK * BATCH)   // 5676
#define NBLOCKS ((TOTWARPS + 7) / 8)         // 710

// E = 1023*1023 + 1022*1023 + 1023*1022 = 3,137,541 ; N = B*E
#define N_TOTAL 12550164.0

__device__ double g_acc = 0.0;
__device__ unsigned int g_done = 0;

struct V3 { float x, y, z; };

__device__ __forceinline__ V3 vsub(V3 a, V3 b) {
    V3 r; r.x = a.x - b.x; r.y = a.y - b.y; r.z = a.z - b.z; return r;
}
__device__ __forceinline__ V3 vcross(V3 a, V3 b) {
    V3 r;
    r.x = fmaf(a.y, b.z, -a.z * b.y);
    r.y = fmaf(a.z, b.x, -a.x * b.z);
    r.z = fmaf(a.x, b.y, -a.y * b.x);
    return r;
}
__device__ __forceinline__ float vdot(V3 a, V3 b) {
    return fmaf(a.x, b.x, fmaf(a.y, b.y, a.z * b.z));
}
__device__ __forceinline__ float rq(V3 a) {            // rsqrt(max(|a|^2, eps^2))
    return rsqrtf(fmaxf(vdot(a, a), 1e-16f));
}
__device__ __forceinline__ V3 vscale(V3 a, float s) {
    V3 r; r.x = a.x * s; r.y = a.y * s; r.z = a.z * s; return r;
}
__device__ __forceinline__ V3 ldv(const float* __restrict__ p) {
    V3 r; r.x = p[0]; r.y = p[1]; r.z = p[2]; return r;
}
__device__ __forceinline__ V3 shup(V3 v) {
    V3 r;
    r.x = __shfl_up_sync(0xFFFFFFFFu, v.x, 1);
    r.y = __shfl_up_sync(0xFFFFFFFFu, v.y, 1);
    r.z = __shfl_up_sync(0xFFFFFFFFu, v.z, 1);
    return r;
}

struct St {
    const float* row;
    V3 p00, p01, u2prev;
    int d3;
    float m_dh, m_v;
};

__device__ __forceinline__ float quad_row(St& s) {
    const float* __restrict__ nrow = s.row + ROWSTRIDE;
    V3 p10 = ldv(nrow);
    V3 p11 = ldv(nrow + s.d3);

    V3 e1 = vsub(s.p01, s.p00);
    V3 e2 = vsub(p10,  s.p00);
    V3 dd = vsub(p11,  s.p00);

    V3 cA = vcross(dd, e1);          // T1 normal (tl,br,tr)
    V3 cB = vcross(e2, dd);          // T2 normal (tl,bl,br)
    V3 u1 = vscale(cA, rq(cA));
    V3 u2 = vscale(cB, rq(cB));

    // diag + horiz (u2prev==0 at global row 0 -> horiz contributes 0)
    float acc = s.m_dh * (vdot(u1, u2) + vdot(u1, s.u2prev));
    // vert: left quad's u1 via shuffle
    V3 u1l = shup(u1);
    acc = fmaf(s.m_v, vdot(u2, u1l), acc);

    s.p00 = p10; s.p01 = p11; s.u2prev = u2; s.row = nrow;
    return acc;
}

__global__ void __launch_bounds__(256, 5)
nc_fused_kernel(const float* __restrict__ x, float* __restrict__ out,
                unsigned int nblocks) {
    const int lane = threadIdx.x & 31;
    const int wid  = threadIdx.x >> 5;
    const int W    = blockIdx.x * 8 + wid;

    float sum = 0.0f;
    if (W < TOTWARPS) {
        const int strip = W % NSTRIP;
        const int rest  = W / NSTRIP;
        const int chunk = rest % NCHUNK;
        const int bb    = rest / NCHUNK;

        const int c  = strip * 31 + lane;       // 0..1023
        const int r0 = chunk * ROWS;
        const bool cvalid = (c < G - 1);        // c <= 1022

        St s;
        s.d3   = cvalid ? 3 : 0;                // invalid lane: clamp to own column
        s.m_dh = (lane < 31) ? 1.0f : 0.0f;     // diag+horiz owner lanes
        s.m_v  = (lane >= 1 && cvalid) ? 1.0f : 0.0f;

        const float* __restrict__ base = x + (size_t)bb * (size_t)G * G * 3;
        s.row = base + ((size_t)r0 * G + c) * 3;
        s.p00 = ldv(s.row);
        s.p01 = ldv(s.row + s.d3);
        s.u2prev = V3{0.f, 0.f, 0.f};
        if (r0 >= 1) {                           // û2 of quad (r0-1, c)
            V3 pm = ldv(s.row - ROWSTRIDE);
            V3 e2p = vsub(s.p00, pm);
            V3 dp  = vsub(s.p01, pm);
            V3 cBp = vcross(e2p, dp);
            s.u2prev = vscale(cBp, rq(cBp));
        }

        const int nrows = min(ROWS, (G - 1) - r0);
        if (nrows == ROWS) {
            #pragma unroll 4
            for (int i = 0; i < ROWS; ++i) sum += quad_row(s);
        } else {
            for (int i = 0; i < nrows; ++i) sum += quad_row(s);
        }
    }

    // ---- block reduction ----
    #pragma unroll
    for (int off = 16; off > 0; off >>= 1)
        sum += __shfl_down_sync(0xFFFFFFFFu, sum, off);

    __shared__ float warp_sums[8];
    if (lane == 0) warp_sums[wid] = sum;
    __syncthreads();

    __shared__ bool is_last;
    if (wid == 0) {
        float sv = (lane < 8) ? warp_sums[lane] : 0.0f;
        #pragma unroll
        for (int off = 4; off > 0; off >>= 1)
            sv += __shfl_down_sync(0xFFFFFFFFu, sv, off);
        if (lane == 0) {
            atomicAdd(&g_acc, (double)sv);
            __threadfence();
            unsigned int done = atomicInc(&g_done, nblocks - 1);
            is_last = (done == nblocks - 1);
        }
    }
    __syncthreads();

    if (is_last && threadIdx.x == 0) {
        double acc = atomicAdd(&g_acc, 0.0);      // coherent read
        out[0] = (float)(1.0 - acc / N_TOTAL);    // loss = 1 - mean(cos)
        __threadfence();
        g_acc = 0.0;                               // g_done wrapped via atomicInc
    }
}

extern "C" void kernel_launch(void* const* d_in, const int* in_sizes, int n_in,
                              void* d_out, int out_size) {
    const float* x = (const float*)d_in[0];
    float* out = (float*)d_out;

    dim3 block(256, 1, 1);
    dim3 grid(NBLOCKS, 1, 1);   // 710 blocks -> one wave @ 5 CTA/SM
    nc_fused_kernel<<<grid, block>>>(x, out, NBLOCKS);
}